// round 10
// baseline (speedup 1.0000x reference)
#include <cuda_runtime.h>
#include <cuda_bf16.h>
#include <math.h>

// Problem constants
#define BB 8
#define SS 512
#define DD 384
#define BSROWS (BB * SS)          // 4096
#define MAXR 128                  // cap on relevant s2 rows (expected ~8-12)
#define RPAD (MAXR + 16)          // padded rows so multi-pass never reads OOB
#define DCH 96                    // d rows per block
#define NCH (DD / DCH)            // 4
#define TH 384                    // bilinear block size
#define NWARP (TH / 32)           // 12
#define JPMAX 8

typedef unsigned long long ull;

// -------- device scratch (no allocations allowed) --------
__device__ int   g_cnt  = 0;      // raw pair count (clamp at use)
__device__ int   g_ocnt = 0;      // masked-in output rows
__device__ int   g_done = 0;      // bilinear completion counter
__device__ int   g_src[MAXR];
__device__ int   g_dst[MAXR];
__device__ int   g_orow[BSROWS];
__device__ float g_w[MAXR];
__device__ __align__(16) float g_toff[DD];
__device__ __align__(16) float g_base[DD];
__device__ __align__(16) float g_tok[RPAD * DD];
__device__ __align__(16) float g_dep[RPAD * DD];
__device__ __align__(16) float g_u[RPAD * DD];

#define FMA2(acc, a, b) \
    asm("fma.rn.f32x2 %0, %1, %2, %0;" : "+l"(acc) : "l"(a), "l"(b))
#define DUP(p, f) \
    asm("mov.b64 %0, {%1, %1};" : "=l"(p) : "f"(f))
#define PACK2(p, a, b) \
    asm("mov.b64 %0, {%1, %2};" : "=l"(p) : "f"(a), "f"(b))

// ============================================================================
// K1 setup: grid 1536 x 256.
//   - zero out (1 float4/thread, exact coverage)
//   - zero g_u (padded)
//   - build pair list + masked-row list via atomics (order irrelevant)
//   - last block: Wr sum, t_off, base
// Counters were reset by the previous replay's bilinear tail (module-load
// zero-init covers the very first call).
// ============================================================================
__global__ void setup_kernel(const int* __restrict__ heads,
                             const float* __restrict__ Wr,
                             const float* __restrict__ bc,
                             const float* __restrict__ br,
                             float4* __restrict__ out4) {
    const int tid = threadIdx.x;
    const int gid = blockIdx.x * 256 + tid;
    const float4 z = make_float4(0.f, 0.f, 0.f, 0.f);

    out4[gid] = z;                                  // 393216 float4 exact

    if (gid < RPAD * DD / 4)
        reinterpret_cast<float4*>(g_u)[gid] = z;

    if (gid < BSROWS) {
        const int b = gid >> 9;
        const int h = heads[gid];
        if (heads[(b << 9) + h] == 0) {
            int p = atomicAdd(&g_cnt, 1);
            if (p < MAXR) {
                g_src[p] = gid;
                g_dst[p] = (b << 9) + h;
                g_w[p]   = Wr[gid & (SS - 1)];
            }
        }
        if (h == 0) {
            int p = atomicAdd(&g_ocnt, 1);
            g_orow[p] = gid;
        }
    }

    if (blockIdx.x == gridDim.x - 1) {
        __shared__ float sred[256];
        float v = Wr[tid] + Wr[tid + 256];
        sred[tid] = v;
        __syncthreads();
        for (int off = 128; off > 0; off >>= 1) {
            if (tid < off) sred[tid] += sred[tid + off];
            __syncthreads();
        }
        const float sw = sred[0];
        const float b0 = br[0];
        for (int o = tid; o < DD; o += 256) {
            float t = tanhf(bc[o]);
            g_toff[o] = t;
            g_base[o] = t * sw + b0;
        }
    }
}

// ============================================================================
// K2 gather: grid 216 x 256 over RPAD*DD. tok/dep fill (zero-padded rows).
// ============================================================================
__global__ void gather_kernel(const int* __restrict__ tokens,
                              const float* __restrict__ table) {
    const int idx = blockIdx.x * blockDim.x + threadIdx.x;  // < RPAD*DD
    const int j = idx / DD;
    const int d = idx - j * DD;
    const int cntc = min(g_cnt, MAXR);
    float t = 0.f;
    if (j < cntc) t = table[(size_t)tokens[g_src[j]] * DD + d];
    g_tok[idx] = t;
    g_dep[idx] = tanhf(t);   // tanh(0)=0 for padded rows
}

// ============================================================================
// Bilinear bodies: u[jb+j][o] += sum_{d,e} tok[j,d] * Wc[o,d,e] * dep[j,e]
// ============================================================================

// EV=4 path: ETH=96 e-threads (float4 W loads), DPH=4, KIT=24. JP<=6.
template<int JP>
__device__ __forceinline__ void body4(const float* __restrict__ Wc, int jb,
                                      ull (*tok_s)[JPMAX],
                                      float (*red)[NWARP],
                                      float* __restrict__ out) {
    constexpr int R   = 2 * JP;
    constexpr int ETH = 96;
    constexpr int DPH = TH / ETH;       // 4
    constexpr int KIT = DCH / DPH;      // 24

    const int o   = blockIdx.y;
    const int d0  = blockIdx.x * DCH;
    const int tid = threadIdx.x;
    const int et  = tid % ETH;
    const int dph = tid / ETH;

    for (int idx = tid; idx < DCH * JP; idx += TH) {
        int d = idx / JP, q = idx - d * JP;
        float a = g_tok[(jb + 2 * q)     * DD + d0 + d];
        float b = g_tok[(jb + 2 * q + 1) * DD + d0 + d];
        ull p; PACK2(p, a, b);
        tok_s[d][q] = p;
    }
    __syncthreads();

    ull m[JP][4];
    #pragma unroll
    for (int q = 0; q < JP; q++)
        #pragma unroll
        for (int c = 0; c < 4; c++) m[q][c] = 0ULL;

    const float4* __restrict__ Wp =
        reinterpret_cast<const float4*>(Wc + ((size_t)o * DD + d0) * DD) + et;
    const int rs = DD / 4;              // 96

    float4 wbuf[3];
    wbuf[0] = __ldcs(&Wp[(size_t)dph * rs]);
    wbuf[1] = __ldcs(&Wp[(size_t)(dph + DPH) * rs]);
    wbuf[2] = __ldcs(&Wp[(size_t)(dph + 2 * DPH) * rs]);

    #pragma unroll
    for (int k = 0; k < KIT; k++) {
        float4 w = wbuf[k % 3];
        if (k + 3 < KIT)
            wbuf[k % 3] = __ldcs(&Wp[(size_t)(dph + DPH * (k + 3)) * rs]);
        const int d = dph + DPH * k;
        ull wd0, wd1, wd2, wd3;
        DUP(wd0, w.x); DUP(wd1, w.y); DUP(wd2, w.z); DUP(wd3, w.w);
        #pragma unroll
        for (int q2 = 0; q2 < JP / 2; q2++) {
            ulonglong2 tp = *reinterpret_cast<const ulonglong2*>(&tok_s[d][2 * q2]);
            FMA2(m[2 * q2][0], tp.x, wd0);
            FMA2(m[2 * q2][1], tp.x, wd1);
            FMA2(m[2 * q2][2], tp.x, wd2);
            FMA2(m[2 * q2][3], tp.x, wd3);
            FMA2(m[2 * q2 + 1][0], tp.y, wd0);
            FMA2(m[2 * q2 + 1][1], tp.y, wd1);
            FMA2(m[2 * q2 + 1][2], tp.y, wd2);
            FMA2(m[2 * q2 + 1][3], tp.y, wd3);
        }
        if constexpr (JP & 1) {
            ull tp = tok_s[d][JP - 1];
            FMA2(m[JP - 1][0], tp, wd0);
            FMA2(m[JP - 1][1], tp, wd1);
            FMA2(m[JP - 1][2], tp, wd2);
            FMA2(m[JP - 1][3], tp, wd3);
        }
    }

    // epilogue: dep contraction at e = 4*et + c, coalesced float4 dep loads
    float s[R];
    #pragma unroll
    for (int r = 0; r < R; r++) s[r] = 0.f;
    #pragma unroll
    for (int q = 0; q < JP; q++) {
        float4 dA = reinterpret_cast<const float4*>(&g_dep[(jb + 2 * q) * DD])[et];
        float4 dB = reinterpret_cast<const float4*>(&g_dep[(jb + 2 * q + 1) * DD])[et];
        #pragma unroll
        for (int c = 0; c < 4; c++) {
            float mx, my;
            asm("mov.b64 {%0, %1}, %2;" : "=f"(mx), "=f"(my) : "l"(m[q][c]));
            float da = (c == 0) ? dA.x : (c == 1) ? dA.y : (c == 2) ? dA.z : dA.w;
            float db = (c == 0) ? dB.x : (c == 1) ? dB.y : (c == 2) ? dB.z : dB.w;
            s[2 * q]     += mx * da;
            s[2 * q + 1] += my * db;
        }
    }

    const int lane = tid & 31;
    const int warp = tid >> 5;
    #pragma unroll
    for (int r = 0; r < R; r++) {
        float v = s[r];
        #pragma unroll
        for (int off = 16; off > 0; off >>= 1)
            v += __shfl_down_sync(0xffffffffu, v, off);
        if (lane == 0) red[r][warp] = v;
    }
    __syncthreads();
    if (tid < R) {
        float acc = 0.f;
        #pragma unroll
        for (int wz = 0; wz < NWARP; wz++) acc += red[tid][wz];
        atomicAdd(&g_u[(jb + tid) * DD + o], acc);
    }
    __syncthreads();
}

// EV=2 path: ETH=192 (float2 W loads), DPH=2, KIT=48. JP=7,8.
template<int JP>
__device__ __forceinline__ void body2(const float* __restrict__ Wc, int jb,
                                      ull (*tok_s)[JPMAX],
                                      float (*red)[NWARP]) {
    constexpr int R   = 2 * JP;
    constexpr int ETH = 192;
    constexpr int DPH = TH / ETH;       // 2
    constexpr int KIT = DCH / DPH;      // 48

    const int o   = blockIdx.y;
    const int d0  = blockIdx.x * DCH;
    const int tid = threadIdx.x;
    const int et  = tid % ETH;
    const int dph = tid / ETH;

    for (int idx = tid; idx < DCH * JP; idx += TH) {
        int d = idx / JP, q = idx - d * JP;
        float a = g_tok[(jb + 2 * q)     * DD + d0 + d];
        float b = g_tok[(jb + 2 * q + 1) * DD + d0 + d];
        ull p; PACK2(p, a, b);
        tok_s[d][q] = p;
    }
    __syncthreads();

    ull m[JP][2];
    #pragma unroll
    for (int q = 0; q < JP; q++) { m[q][0] = 0ULL; m[q][1] = 0ULL; }

    const float2* __restrict__ Wp =
        reinterpret_cast<const float2*>(Wc + ((size_t)o * DD + d0) * DD) + et;
    const int rs = DD / 2;

    float2 wbuf[4];
    #pragma unroll
    for (int p = 0; p < 3; p++)
        wbuf[p] = __ldcs(&Wp[(size_t)(dph + DPH * p) * rs]);

    #pragma unroll
    for (int k = 0; k < KIT; k++) {
        if (k + 3 < KIT)
            wbuf[(k + 3) & 3] = __ldcs(&Wp[(size_t)(dph + DPH * (k + 3)) * rs]);
        float2 w = wbuf[k & 3];
        const int d = dph + DPH * k;
        ull wd0, wd1;
        DUP(wd0, w.x); DUP(wd1, w.y);
        #pragma unroll
        for (int q2 = 0; q2 < JP / 2; q2++) {
            ulonglong2 tp = *reinterpret_cast<const ulonglong2*>(&tok_s[d][2 * q2]);
            FMA2(m[2 * q2][0], tp.x, wd0);
            FMA2(m[2 * q2][1], tp.x, wd1);
            FMA2(m[2 * q2 + 1][0], tp.y, wd0);
            FMA2(m[2 * q2 + 1][1], tp.y, wd1);
        }
        if constexpr (JP & 1) {
            ull tp = tok_s[d][JP - 1];
            FMA2(m[JP - 1][0], tp, wd0);
            FMA2(m[JP - 1][1], tp, wd1);
        }
    }

    float s[R];
    #pragma unroll
    for (int r = 0; r < R; r++) s[r] = 0.f;
    #pragma unroll
    for (int q = 0; q < JP; q++) {
        #pragma unroll
        for (int c = 0; c < 2; c++) {
            float mx, my;
            asm("mov.b64 {%0, %1}, %2;" : "=f"(mx), "=f"(my) : "l"(m[q][c]));
            int e = 2 * et + c;
            s[2 * q]     += mx * g_dep[(jb + 2 * q)     * DD + e];
            s[2 * q + 1] += my * g_dep[(jb + 2 * q + 1) * DD + e];
        }
    }

    const int lane = tid & 31;
    const int warp = tid >> 5;
    #pragma unroll
    for (int r = 0; r < R; r++) {
        float v = s[r];
        #pragma unroll
        for (int off = 16; off > 0; off >>= 1)
            v += __shfl_down_sync(0xffffffffu, v, off);
        if (lane == 0) red[r][warp] = v;
    }
    __syncthreads();
    if (tid < R) {
        float acc = 0.f;
        #pragma unroll
        for (int wz = 0; wz < NWARP; wz++) acc += red[tid][wz];
        atomicAdd(&g_u[(jb + tid) * DD + o], acc);
    }
    __syncthreads();
}

// ============================================================================
// K3: bilinear + fused finalize in the last-finished block.
// ============================================================================
__global__ void __launch_bounds__(TH, 2)
bilinear_kernel(const float* __restrict__ Wc,
                const float* __restrict__ bc,
                float* __restrict__ out) {
    const int cnt = min(g_cnt, MAXR);
    const int tid = threadIdx.x;

    __shared__ __align__(16) ull tok_s[DCH][JPMAX];
    __shared__ float red[2 * JPMAX][NWARP];

    if (cnt > 0) {
        if (cnt <= 12) {
            switch ((cnt + 1) >> 1) {
                case 1: body4<1>(Wc, 0, tok_s, red, out); break;
                case 2: body4<2>(Wc, 0, tok_s, red, out); break;
                case 3: body4<3>(Wc, 0, tok_s, red, out); break;
                case 4: body4<4>(Wc, 0, tok_s, red, out); break;
                case 5: body4<5>(Wc, 0, tok_s, red, out); break;
                default: body4<6>(Wc, 0, tok_s, red, out); break;
            }
        } else if (cnt <= 14) {
            body2<7>(Wc, 0, tok_s, red);
        } else if (cnt <= 16) {
            body2<8>(Wc, 0, tok_s, red);
        } else {
            const int npass = (cnt + 11) / 12;
            for (int p = 0; p < npass; p++)
                body4<6>(Wc, 12 * p, tok_s, red, out);
        }
    }

    // ---- completion counter; last block finalizes + resets ----
    __threadfence();
    __syncthreads();
    __shared__ int slast;
    if (tid == 0)
        slast = (atomicAdd(&g_done, 1) == (int)(gridDim.x * gridDim.y) - 1);
    __syncthreads();
    if (slast) {
        const int o = tid;                 // TH == DD
        const int ocnt = g_ocnt;
        const float b = bc[o];
        const float t_off = g_toff[o];
        const float base = g_base[o];
        for (int r = 0; r < ocnt; r++) {
            const int row = g_orow[r];
            float v = base;
            for (int j = 0; j < cnt; j++) {
                if (g_dst[j] == row)
                    v += (tanhf(g_u[j * DD + o] + b) - t_off) * g_w[j];
            }
            out[(size_t)row * DD + o] = v;
        }
        __syncthreads();
        if (tid == 0) { g_cnt = 0; g_ocnt = 0; g_done = 0; }
    }
}

// ============================================================================
// launch
// ============================================================================
extern "C" void kernel_launch(void* const* d_in, const int* in_sizes, int n_in,
                              void* d_out, int out_size) {
    const int*   tokens = (const int*)d_in[0];
    // d_in[1] = dep_types: unused (discarded in reference)
    const int*   heads  = (const int*)d_in[2];
    const float* table  = (const float*)d_in[3];
    const float* Wc     = (const float*)d_in[4];
    const float* bc     = (const float*)d_in[5];
    const float* Wr     = (const float*)d_in[6];
    const float* br     = (const float*)d_in[7];
    float* out = (float*)d_out;

    setup_kernel<<<BSROWS * DD / 4 / 256, 256>>>(heads, Wr, bc, br, (float4*)out);
    gather_kernel<<<RPAD * DD / 256, 256>>>(tokens, table);
    dim3 g3(NCH, DD);
    bilinear_kernel<<<g3, TH>>>(Wc, bc, out);
}

// round 12
// speedup vs baseline: 1.1463x; 1.1463x over previous
#include <cuda_runtime.h>
#include <cuda_bf16.h>
#include <math.h>

// Problem constants
#define BB 8
#define SS 512
#define DD 384
#define BSROWS (BB * SS)          // 4096
#define MAXR 128                  // cap on relevant s2 rows (expected ~8-12)
#define DCH 96                    // d rows per block
#define NCH (DD / DCH)            // 4
#define TH 384                    // bilinear block size
#define NWARP (TH / 32)           // 12
#define JPMAX 8

typedef unsigned long long ull;

// -------- device scratch (no allocations allowed) --------
__device__ int   g_cnt;
__device__ int   g_ocnt;
__device__ int   g_src[MAXR];
__device__ int   g_dst[MAXR];
__device__ int   g_orow[BSROWS];
__device__ float g_w[MAXR];
__device__ __align__(16) float g_toff[DD];
__device__ __align__(16) float g_base[DD];
__device__ __align__(16) float g_tok[MAXR * DD];
__device__ __align__(16) float g_dep[MAXR * DD];
__device__ __align__(16) float g_u[MAXR * DD];

#define FMA2(acc, a, b) \
    asm("fma.rn.f32x2 %0, %1, %2, %0;" : "+l"(acc) : "l"(a), "l"(b))
#define DUP(p, f) \
    asm("mov.b64 %0, {%1, %1};" : "=l"(p) : "f"(f))
#define PACK2(p, a, b) \
    asm("mov.b64 %0, {%1, %2};" : "=l"(p) : "f"(a), "f"(b))

// ============================================================================
// K1a: one block, 512 threads. Sequential scan part only.
// ============================================================================
__global__ void prep_scan_kernel(const int* __restrict__ heads,
                                 const float* __restrict__ bc,
                                 const float* __restrict__ Wr,
                                 const float* __restrict__ br) {
    __shared__ float swred[SS];
    __shared__ int cnts[SS];
    const int tid = threadIdx.x;

    if (tid == 0) g_ocnt = 0;

    // ---- sum of Wr over S ----
    swred[tid] = Wr[tid];
    __syncthreads();
    for (int off = 256; off > 0; off >>= 1) {
        if (tid < off) swred[tid] += swred[tid + off];
        __syncthreads();
    }
    const float sw = swred[0];

    // ---- t_off / base ----
    if (tid < DD) {
        float t = tanhf(bc[tid]);
        g_toff[tid] = t;
        g_base[tid] = t * sw + br[0];
    }

    // ---- deterministic pair list via prefix scan (8 items/thread) ----
    const int base_i = tid * 8;
    int c = 0;
    #pragma unroll
    for (int k = 0; k < 8; k++) {
        int i = base_i + k;
        int h = heads[i];
        int b = i >> 9;
        if (heads[(b << 9) + h] == 0) c++;
    }
    cnts[tid] = c;
    __syncthreads();
    for (int off = 1; off < SS; off <<= 1) {
        int v = (tid >= off) ? cnts[tid - off] : 0;
        __syncthreads();
        cnts[tid] += v;
        __syncthreads();
    }
    const int start = cnts[tid] - c;
    const int total = cnts[SS - 1];
    if (tid == 0) g_cnt = (total > MAXR) ? MAXR : total;

    int pos = start;
    #pragma unroll
    for (int k = 0; k < 8; k++) {
        int i = base_i + k;
        int h = heads[i];
        int b = i >> 9;
        if (heads[(b << 9) + h] == 0) {
            if (pos < MAXR) {
                g_src[pos] = i;
                g_dst[pos] = (b << 9) + h;
                g_w[pos]   = Wr[i & (SS - 1)];
            }
            pos++;
        }
    }
}

// ============================================================================
// K1b: parallel gather + zero(u) + zero(out) + masked-row collection.
//      grid 192 x 256 over MAXR*DD elements. Each thread also zeroes 8
//      float4 of the output (dependency-free stores) and the first BSROWS
//      threads collect rows with heads[row]==0 into g_orow.
// ============================================================================
__global__ void gather_kernel(const int* __restrict__ tokens,
                              const int* __restrict__ heads,
                              const float* __restrict__ table,
                              float4* __restrict__ out4) {
    const int idx = blockIdx.x * blockDim.x + threadIdx.x;  // < MAXR*DD = 49152

    // zero the output: 8 float4 per thread, 49152*8 = 393216 = BSROWS*DD/4
    const float4 z = make_float4(0.f, 0.f, 0.f, 0.f);
    #pragma unroll
    for (int k = 0; k < 8; k++)
        out4[idx + 49152 * k] = z;

    if (idx < BSROWS) {
        if (heads[idx] == 0) {
            int p = atomicAdd(&g_ocnt, 1);
            g_orow[p] = idx;
        }
    }

    g_u[idx] = 0.f;
    const int j = idx / DD;
    const int d = idx - j * DD;
    float t = 0.f;
    if (j < g_cnt) t = table[(size_t)tokens[g_src[j]] * DD + d];
    g_tok[idx] = t;
    g_dep[idx] = tanhf(t);   // tanh(0)=0 for padded rows
}

// ============================================================================
// Bilinear body: u[jb+j][o] += sum_{d,e} tok[j,d] * Wc[o,d,e] * dep[j,e]
//   JP = j-pairs processed (rows R = 2*JP), EV = e floats per thread.
//   tok j-pairs in smem ({tok[j0,d],tok[j1,d]} packed, row stride JPMAX);
//   W value register-duplicated; 4-deep W prefetch ring.
// ============================================================================
template<int JP, int EV>
__device__ __forceinline__ void bilinear_body(const float* __restrict__ Wc,
                                              int jb,
                                              ull (*tok_s)[JPMAX],
                                              float (*red)[NWARP]) {
    constexpr int R   = 2 * JP;
    constexpr int ETH = DD / EV;        // e-threads per d-phase
    constexpr int DPH = TH / ETH;       // d-phases
    constexpr int KIT = DCH / DPH;      // d iterations per thread

    const int o   = blockIdx.y;
    const int d0  = blockIdx.x * DCH;
    const int tid = threadIdx.x;
    const int et  = tid % ETH;
    const int dph = tid / ETH;

    // fill tok j-pairs
    for (int idx = tid; idx < DCH * JP; idx += TH) {
        int d = idx / JP, q = idx - d * JP;
        float a = g_tok[(jb + 2 * q)     * DD + d0 + d];
        float b = g_tok[(jb + 2 * q + 1) * DD + d0 + d];
        ull p; PACK2(p, a, b);
        tok_s[d][q] = p;
    }
    __syncthreads();

    ull m[JP][EV];
    #pragma unroll
    for (int q = 0; q < JP; q++)
        #pragma unroll
        for (int c = 0; c < EV; c++) m[q][c] = 0ULL;

    const float* Wbase = Wc + ((size_t)o * DD + d0) * DD;

    if constexpr (EV == 4) {
        const float4* __restrict__ Wp = reinterpret_cast<const float4*>(Wbase) + et;
        const int rs = DD / 4;
        float4 wbuf[4];
        #pragma unroll
        for (int p = 0; p < 3; p++)
            wbuf[p] = (p < KIT) ? __ldcs(&Wp[(size_t)(dph + DPH * p) * rs])
                                : make_float4(0.f, 0.f, 0.f, 0.f);
        #pragma unroll
        for (int k = 0; k < KIT; k++) {
            if (k + 3 < KIT)
                wbuf[(k + 3) & 3] = __ldcs(&Wp[(size_t)(dph + DPH * (k + 3)) * rs]);
            float4 w = wbuf[k & 3];
            const int d = dph + DPH * k;
            ull wd0, wd1, wd2, wd3;
            DUP(wd0, w.x); DUP(wd1, w.y); DUP(wd2, w.z); DUP(wd3, w.w);
            #pragma unroll
            for (int q = 0; q < JP; q++) {
                ull tp = tok_s[d][q];
                FMA2(m[q][0], tp, wd0);
                FMA2(m[q][1], tp, wd1);
                FMA2(m[q][2], tp, wd2);
                FMA2(m[q][3], tp, wd3);
            }
        }
    } else {
        const float2* __restrict__ Wp = reinterpret_cast<const float2*>(Wbase) + et;
        const int rs = DD / 2;
        float2 wbuf[4];
        #pragma unroll
        for (int p = 0; p < 3; p++)
            wbuf[p] = (p < KIT) ? __ldcs(&Wp[(size_t)(dph + DPH * p) * rs])
                                : make_float2(0.f, 0.f);
        #pragma unroll
        for (int k = 0; k < KIT; k++) {
            if (k + 3 < KIT)
                wbuf[(k + 3) & 3] = __ldcs(&Wp[(size_t)(dph + DPH * (k + 3)) * rs]);
            float2 w = wbuf[k & 3];
            const int d = dph + DPH * k;
            ull wd0, wd1;
            DUP(wd0, w.x); DUP(wd1, w.y);
            #pragma unroll
            for (int q = 0; q < JP; q++) {
                ull tp = tok_s[d][q];
                FMA2(m[q][0], tp, wd0);
                FMA2(m[q][1], tp, wd1);
            }
        }
    }

    // apply dep at this thread's e-columns, accumulate per row
    float s[R];
    #pragma unroll
    for (int r = 0; r < R; r++) s[r] = 0.f;
    #pragma unroll
    for (int q = 0; q < JP; q++) {
        #pragma unroll
        for (int c = 0; c < EV; c++) {
            float mx, my;
            asm("mov.b64 {%0, %1}, %2;" : "=f"(mx), "=f"(my) : "l"(m[q][c]));
            int e = EV * et + c;
            s[2 * q]     += mx * g_dep[(jb + 2 * q)     * DD + e];
            s[2 * q + 1] += my * g_dep[(jb + 2 * q + 1) * DD + e];
        }
    }

    const int lane = tid & 31;
    const int warp = tid >> 5;
    #pragma unroll
    for (int r = 0; r < R; r++) {
        float v = s[r];
        #pragma unroll
        for (int off = 16; off > 0; off >>= 1)
            v += __shfl_down_sync(0xffffffffu, v, off);
        if (lane == 0) red[r][warp] = v;
    }
    __syncthreads();
    if (tid < R) {
        float acc = 0.f;
        #pragma unroll
        for (int wz = 0; wz < NWARP; wz++) acc += red[tid][wz];
        atomicAdd(&g_u[(jb + tid) * DD + o], acc);
    }
    __syncthreads();
}

// ============================================================================
// K3: single bilinear kernel, exact-JP dispatch on cnt.
// ============================================================================
__global__ void __launch_bounds__(TH, 2)
bilinear_kernel(const float* __restrict__ Wc) {
    const int cnt = g_cnt;
    if (cnt == 0) return;

    __shared__ __align__(16) ull tok_s[DCH][JPMAX];
    __shared__ float red[2 * JPMAX][NWARP];

    if (cnt <= 16) {
        switch ((cnt + 1) >> 1) {
            case 1: bilinear_body<1, 4>(Wc, 0, tok_s, red); break;
            case 2: bilinear_body<2, 4>(Wc, 0, tok_s, red); break;
            case 3: bilinear_body<3, 4>(Wc, 0, tok_s, red); break;
            case 4: bilinear_body<4, 4>(Wc, 0, tok_s, red); break;
            case 5: bilinear_body<5, 2>(Wc, 0, tok_s, red); break;
            case 6: bilinear_body<6, 2>(Wc, 0, tok_s, red); break;
            case 7: bilinear_body<7, 2>(Wc, 0, tok_s, red); break;
            default: bilinear_body<8, 2>(Wc, 0, tok_s, red); break;
        }
    } else {
        const int npass = (cnt + 15) / 16;
        for (int p = 0; p < npass; p++)
            bilinear_body<8, 2>(Wc, 16 * p, tok_s, red);
    }
}

// ============================================================================
// K4: fill masked-in rows: out[row,:] = base + scatter contribs.
//     grid-stride over g_orow (expected ~8 rows). Full-row overwrite
//     (rest of out already zeroed by gather_kernel).
// ============================================================================
__global__ void fill_rows_kernel(const float* __restrict__ bc,
                                 float* __restrict__ out) {
    const int o = threadIdx.x;
    const int cnt = g_cnt;
    const int ocnt = g_ocnt;
    for (int r = blockIdx.x; r < ocnt; r += gridDim.x) {
        const int row = g_orow[r];
        float v = g_base[o];
        for (int j = 0; j < cnt; j++) {
            if (g_dst[j] == row) {
                float u = g_u[j * DD + o];
                v += (tanhf(u + bc[o]) - g_toff[o]) * g_w[j];
            }
        }
        out[(size_t)row * DD + o] = v;
    }
}

// ============================================================================
// launch
// ============================================================================
extern "C" void kernel_launch(void* const* d_in, const int* in_sizes, int n_in,
                              void* d_out, int out_size) {
    const int*   tokens = (const int*)d_in[0];
    // d_in[1] = dep_types: unused (discarded in reference)
    const int*   heads  = (const int*)d_in[2];
    const float* table  = (const float*)d_in[3];
    const float* Wc     = (const float*)d_in[4];
    const float* bc     = (const float*)d_in[5];
    const float* Wr     = (const float*)d_in[6];
    const float* br     = (const float*)d_in[7];
    float* out = (float*)d_out;

    prep_scan_kernel<<<1, SS>>>(heads, bc, Wr, br);
    gather_kernel<<<(MAXR * DD) / 256, 256>>>(tokens, heads, table, (float4*)out);
    dim3 g3(NCH, DD);
    bilinear_kernel<<<g3, TH>>>(Wc);
    fill_rows_kernel<<<64, DD>>>(bc, out);
}